// round 15
// baseline (speedup 1.0000x reference)
#include <cuda_runtime.h>
#include <cuda_fp16.h>
#include <math.h>
#include <stdint.h>

// Problem dims
#define DIM     768
#define HEADS   12
#define HD      64
#define HIDDEN  3072
#define SEQ     1024
#define BATCHN  8
#define TOK     (BATCHN*SEQ)   // 8192
#define QKVDIM  (3*DIM)        // 2304
#define NBH     (BATCHN*HEADS) // 96

// fp16 GEMM tiling: 3-stage cp.async ring
#define BKH      64
#define HSTRIDE  72
#define GEMM_SMEM_128 (3 * (128 + 128) * HSTRIDE * 2)   // 110592 B
#define GEMM_SMEM_64  (3 * (64 + 128) * HSTRIDE * 2)    //  82944 B

// fp16 flash smem (halves): Q | KV0(K,V) | KV1(K,V)
#define FQ_STRIDE 72
#define FTILE_H   (128 * FQ_STRIDE)
#define FLASH_SMEM (5 * FTILE_H * 2)       // 92160 B -> 2 CTAs/SM

#define LOG2E 1.44269504088896f

// ---------------- scratch ----------------
__device__ __half g_h1h[TOK*DIM];
__device__ __half g_h2h[TOK*DIM];
__device__ __half g_olinh[TOK*DIM];
__device__ __half g_h3h[(size_t)TOK*HIDDEN];
__device__ __half g_qkvh[(size_t)TOK*QKVDIM];
__device__ float  g_x2[TOK*DIM];
__device__ __half g_qkvwh[QKVDIM*DIM];
__device__ __half g_projwh[DIM*DIM];
__device__ __half g_fc1wh[HIDDEN*DIM];
__device__ __half g_fc2wh[DIM*HIDDEN];

// ---------------- helpers ----------------
__device__ __forceinline__ void mma16(float* d, const uint32_t* a, uint32_t b0, uint32_t b1) {
    asm volatile(
        "mma.sync.aligned.m16n8k16.row.col.f32.f16.f16.f32 "
        "{%0,%1,%2,%3}, {%4,%5,%6,%7}, {%8,%9}, {%0,%1,%2,%3};"
        : "+f"(d[0]), "+f"(d[1]), "+f"(d[2]), "+f"(d[3])
        : "r"(a[0]), "r"(a[1]), "r"(a[2]), "r"(a[3]), "r"(b0), "r"(b1));
}
__device__ __forceinline__ void ldsm4(uint32_t* r, uint32_t addr) {
    asm volatile("ldmatrix.sync.aligned.m8n8.x4.shared.b16 {%0,%1,%2,%3}, [%4];"
        : "=r"(r[0]), "=r"(r[1]), "=r"(r[2]), "=r"(r[3]) : "r"(addr));
}
__device__ __forceinline__ float gelu1(float x) {
    return 0.5f * x * (1.f + erff(x * 0.70710678118654752f));
}
__device__ __forceinline__ void cp16h(__half* dst, const __half* src) {
    unsigned d = (unsigned)__cvta_generic_to_shared(dst);
    asm volatile("cp.async.cg.shared.global [%0], [%1], 16;\n" :: "r"(d), "l"(src));
}
__device__ __forceinline__ void cp_commit() {
    asm volatile("cp.async.commit_group;\n");
}
template<int N>
__device__ __forceinline__ void cp_wait() {
    asm volatile("cp.async.wait_group %0;\n" :: "n"(N));
}

// ---------------- fused fp32 -> fp16 converter ----------------
__global__ void cvt_all(const float4* __restrict__ s0, __half2* __restrict__ d0, int n0,
                        const float4* __restrict__ s1, __half2* __restrict__ d1, int n1,
                        const float4* __restrict__ s2, __half2* __restrict__ d2, int n2,
                        const float4* __restrict__ s3, __half2* __restrict__ d3, int n3) {
    int i = blockIdx.x * blockDim.x + threadIdx.x;
    const float4* s; __half2* d;
    if (i < n0) { s = s0; d = d0; }
    else if ((i -= n0) < n1) { s = s1; d = d1; }
    else if ((i -= n1) < n2) { s = s2; d = d2; }
    else if ((i -= n2) < n3) { s = s3; d = d3; }
    else return;
    float4 v = s[i];
    d[2*i]   = __floats2half2_rn(v.x, v.y);
    d[2*i+1] = __floats2half2_rn(v.z, v.w);
}

// ---------------- LayerNorm: one warp per row, shuffle-only ----------------
__global__ void ln_kernel(const float* __restrict__ in,
                          const float* __restrict__ gam,
                          const float* __restrict__ bet,
                          __half* __restrict__ out) {
    const int warp = threadIdx.x >> 5, lane = threadIdx.x & 31;
    const int row = blockIdx.x * 8 + warp;
    const float* x = in + (size_t)row * DIM;

    float4 v[6];
    float s = 0.f, q = 0.f;
    #pragma unroll
    for (int i = 0; i < 6; i++) {
        v[i] = *(const float4*)(x + i * 128 + lane * 4);
        s += v[i].x + v[i].y + v[i].z + v[i].w;
        q += v[i].x*v[i].x + v[i].y*v[i].y + v[i].z*v[i].z + v[i].w*v[i].w;
    }
    #pragma unroll
    for (int o = 16; o > 0; o >>= 1) {
        s += __shfl_xor_sync(0xffffffffu, s, o);
        q += __shfl_xor_sync(0xffffffffu, q, o);
    }
    const float mu  = s * (1.0f / DIM);
    const float var = q * (1.0f / DIM) - mu * mu;
    const float inv = rsqrtf(var + 1e-5f);

    __half* o = out + (size_t)row * DIM;
    #pragma unroll
    for (int i = 0; i < 6; i++) {
        const int c = i * 128 + lane * 4;
        float4 g = *(const float4*)(gam + c);
        float4 b = *(const float4*)(bet + c);
        __half2 h0 = __floats2half2_rn((v[i].x - mu) * inv * g.x + b.x,
                                       (v[i].y - mu) * inv * g.y + b.y);
        __half2 h1 = __floats2half2_rn((v[i].z - mu) * inv * g.z + b.z,
                                       (v[i].w - mu) * inv * g.w + b.w);
        uint2 pk; pk.x = *(uint32_t*)&h0; pk.y = *(uint32_t*)&h1;
        *(uint2*)(o + c) = pk;
    }
}

// ---------------- FP16 MMA GEMM (TN): 3-stage ring, MROWS template ----------
enum { EPI_BIAS = 1, EPI_BIAS_RES = 2, EPI_BIAS_GELU = 3 };

template<int EPI, int OUTH, int MROWS>
__global__ __launch_bounds__(256, 2)
void hgemm_tn_kernel(const __half* __restrict__ A, int lda,
                     const __half* __restrict__ W, int ldw,
                     void* __restrict__ Cv, int ldc, int K,
                     const float* __restrict__ bias,
                     const float* __restrict__ res, int ldres) {
    constexpr int MT = MROWS / 32;            // m-tiles per warp (4 or 2)
    constexpr int A_STAGE = MROWS * HSTRIDE;  // halves
    constexpr int SP = (MROWS + 128) * HSTRIDE;

    extern __shared__ __half smh[];
    const uint32_t smbase = (uint32_t)__cvta_generic_to_shared(smh);
    const int m0 = blockIdx.y * MROWS, n0 = blockIdx.x * 128;
    const int tid  = threadIdx.x;
    const int lane = tid & 31;
    const int warp = tid >> 5;
    const int m0w  = (warp >> 2) * (MROWS / 2);
    const int n0w  = (warp & 3) * 32;
    const int gid  = lane >> 2;
    const int qid  = lane & 3;
    const int i8   = lane >> 3;
    const int r8   = lane & 7;

    const int crow0 = tid >> 3;               // 0..31
    const int cgr   = tid & 7;

    float acc[MT][4][4];
    #pragma unroll
    for (int i = 0; i < MT; i++)
        #pragma unroll
        for (int j = 0; j < 4; j++)
            #pragma unroll
            for (int r = 0; r < 4; r++) acc[i][j][r] = 0.f;

    const int nch = K / BKH;

    auto load_chunk = [&](int j) {
        __half* as = smh + (j % 3) * SP;
        __half* ws = as + A_STAGE;
        const __half* Aj = A + (size_t)m0 * lda + j * BKH + cgr * 8;
        const __half* Wj = W + (size_t)n0 * ldw + j * BKH + cgr * 8;
        #pragma unroll
        for (int r = 0; r < MROWS / 32; r++) {
            int row = crow0 + r * 32;
            cp16h(&as[row * HSTRIDE + cgr * 8], Aj + (size_t)row * lda);
        }
        #pragma unroll
        for (int r = 0; r < 4; r++) {
            int row = crow0 + r * 32;
            cp16h(&ws[row * HSTRIDE + cgr * 8], Wj + (size_t)row * ldw);
        }
    };

    load_chunk(0);
    cp_commit();
    load_chunk(1);
    cp_commit();

    for (int i = 0; i < nch; i++) {
        cp_wait<1>();
        __syncthreads();

        if (i + 2 < nch) load_chunk(i + 2);
        cp_commit();

        const uint32_t abase = smbase + (uint32_t)((i % 3) * SP) * 2u;
        const uint32_t bbase = abase + (uint32_t)A_STAGE * 2u;
        #pragma unroll
        for (int ks = 0; ks < 4; ks++) {
            uint32_t af[MT][4];
            #pragma unroll
            for (int mt = 0; mt < MT; mt++) {
                int row = m0w + mt * 16 + (i8 & 1) * 8 + r8;
                int kc  = ks * 16 + (i8 >> 1) * 8;
                ldsm4(af[mt], abase + (uint32_t)(row * HSTRIDE + kc) * 2u);
            }
            uint32_t bf[8];
            #pragma unroll
            for (int j = 0; j < 2; j++) {
                int nrow = n0w + (2 * j + (i8 >> 1)) * 8 + r8;
                int kc   = ks * 16 + (i8 & 1) * 8;
                ldsm4(&bf[4 * j], bbase + (uint32_t)(nrow * HSTRIDE + kc) * 2u);
            }
            #pragma unroll
            for (int nt = 0; nt < 4; nt++)
                #pragma unroll
                for (int mt = 0; mt < MT; mt++)
                    mma16(acc[mt][nt], af[mt], bf[nt * 2], bf[nt * 2 + 1]);
        }
    }

    #pragma unroll
    for (int mt = 0; mt < MT; mt++) {
        #pragma unroll
        for (int nt = 0; nt < 4; nt++) {
            int row = m0 + m0w + mt * 16 + gid;
            int col = n0 + n0w + nt * 8 + qid * 2;
            float2 v0, v1;
            v0.x = acc[mt][nt][0]; v0.y = acc[mt][nt][1];
            v1.x = acc[mt][nt][2]; v1.y = acc[mt][nt][3];
            {
                float2 bb = *(const float2*)(bias + col);
                v0.x += bb.x; v0.y += bb.y; v1.x += bb.x; v1.y += bb.y;
            }
            if (EPI == EPI_BIAS_RES) {
                float2 r0 = *(const float2*)(res + (size_t)row * ldres + col);
                float2 r1 = *(const float2*)(res + (size_t)(row + 8) * ldres + col);
                v0.x += r0.x; v0.y += r0.y; v1.x += r1.x; v1.y += r1.y;
            }
            if (EPI == EPI_BIAS_GELU) {
                v0.x = gelu1(v0.x); v0.y = gelu1(v0.y);
                v1.x = gelu1(v1.x); v1.y = gelu1(v1.y);
            }
            if (OUTH) {
                __half2* C = (__half2*)Cv;
                C[((size_t)row * ldc + col) >> 1]       = __floats2half2_rn(v0.x, v0.y);
                C[((size_t)(row + 8) * ldc + col) >> 1] = __floats2half2_rn(v1.x, v1.y);
            } else {
                float* C = (float*)Cv;
                *(float2*)(C + (size_t)row * ldc + col) = v0;
                *(float2*)(C + (size_t)(row + 8) * ldc + col) = v1;
            }
        }
    }
}

// ---------------- FP16 flash attention: reg-P + double-buffered KV (R14) ----------
__global__ __launch_bounds__(256, 2)
void flash_kernel(const __half* __restrict__ qkv, __half* __restrict__ olin) {
    extern __shared__ __half smf[];
    __half* Qs  = smf;
    __half* KV0 = Qs + FTILE_H;
    __half* KV1 = KV0 + 2 * FTILE_H;

    const int bh = blockIdx.y;
    const int b = bh / HEADS, h = bh % HEADS;
    const int m0 = blockIdx.x * 128;
    const __half* Qg = qkv + (size_t)b * SEQ * QKVDIM + h * HD;
    const __half* Kg = Qg + DIM;
    const __half* Vg = Qg + 2 * DIM;

    const int tid = threadIdx.x, lane = tid & 31, warp = tid >> 5;
    const int gid = lane >> 2, qid = lane & 3;
    const int i8 = lane >> 3, r8 = lane & 7;
    const int t4 = lane >> 3;

    const uint32_t qbase = (uint32_t)__cvta_generic_to_shared(Qs);

    auto load_kv = [&](int kc, __half* dst) {
        const __half* Kc = Kg + (size_t)(kc * 128) * QKVDIM;
        const __half* Vc = Vg + (size_t)(kc * 128) * QKVDIM;
        #pragma unroll
        for (int i = 0; i < 4; i++) {
            int f = i * 256 + tid;
            int r = f >> 3, c8 = (f & 7) * 8;
            cp16h(&dst[r * FQ_STRIDE + c8], Kc + (size_t)r * QKVDIM + c8);
            cp16h(&dst[FTILE_H + r * FQ_STRIDE + c8], Vc + (size_t)r * QKVDIM + c8);
        }
    };

    #pragma unroll
    for (int i = 0; i < 4; i++) {
        int f = i * 256 + tid;
        int r = f >> 3, c8 = (f & 7) * 8;
        cp16h(&Qs[r * FQ_STRIDE + c8], Qg + (size_t)(m0 + r) * QKVDIM + c8);
    }
    cp_commit();
    load_kv(0, KV0);
    cp_commit();

    cp_wait<1>();
    __syncthreads();

    const __half2 kscale = __floats2half2_rn(0.125f * LOG2E, 0.125f * LOG2E);
    uint32_t qf[4][4];
    #pragma unroll
    for (int kk = 0; kk < 4; kk++) {
        int row = warp * 16 + (i8 & 1) * 8 + r8;
        int kc  = kk * 16 + (i8 >> 1) * 8;
        ldsm4(qf[kk], qbase + (uint32_t)(row * FQ_STRIDE + kc) * 2u);
        #pragma unroll
        for (int r = 0; r < 4; r++) {
            __half2 t = __hmul2(*(__half2*)&qf[kk][r], kscale);
            qf[kk][r] = *(uint32_t*)&t;
        }
    }

    float m_i[2] = {-1e30f, -1e30f};
    float l_i[2] = {0.f, 0.f};
    float oacc[8][4];
    #pragma unroll
    for (int nt = 0; nt < 8; nt++)
        #pragma unroll
        for (int r = 0; r < 4; r++) oacc[nt][r] = 0.f;

    for (int kc = 0; kc < 8; kc++) {
        __half* cur = (kc & 1) ? KV1 : KV0;
        __half* nxt = (kc & 1) ? KV0 : KV1;

        if (kc + 1 < 8) load_kv(kc + 1, nxt);
        cp_commit();
        cp_wait<1>();
        __syncthreads();

        const uint32_t kbase = (uint32_t)__cvta_generic_to_shared(cur);
        const uint32_t vbase = kbase + (uint32_t)FTILE_H * 2u;

        #pragma unroll
        for (int half = 0; half < 2; half++) {
            const int koff = half * 64;

            float sacc[8][4];
            #pragma unroll
            for (int nt = 0; nt < 8; nt++)
                #pragma unroll
                for (int r = 0; r < 4; r++) sacc[nt][r] = 0.f;
            #pragma unroll
            for (int kk = 0; kk < 4; kk++) {
                #pragma unroll
                for (int j = 0; j < 4; j++) {
                    uint32_t bt[4];
                    int nrow = koff + (2 * j + (i8 >> 1)) * 8 + r8;
                    int kcc  = kk * 16 + (i8 & 1) * 8;
                    ldsm4(bt, kbase + (uint32_t)(nrow * FQ_STRIDE + kcc) * 2u);
                    mma16(sacc[2 * j],     qf[kk], bt[0], bt[1]);
                    mma16(sacc[2 * j + 1], qf[kk], bt[2], bt[3]);
                }
            }

            float mx0 = -1e30f, mx1 = -1e30f;
            #pragma unroll
            for (int nt = 0; nt < 8; nt++) {
                mx0 = fmaxf(mx0, fmaxf(sacc[nt][0], sacc[nt][1]));
                mx1 = fmaxf(mx1, fmaxf(sacc[nt][2], sacc[nt][3]));
            }
            mx0 = fmaxf(mx0, __shfl_xor_sync(0xffffffffu, mx0, 1));
            mx0 = fmaxf(mx0, __shfl_xor_sync(0xffffffffu, mx0, 2));
            mx1 = fmaxf(mx1, __shfl_xor_sync(0xffffffffu, mx1, 1));
            mx1 = fmaxf(mx1, __shfl_xor_sync(0xffffffffu, mx1, 2));

            float mnew0 = fmaxf(m_i[0], mx0);
            float mnew1 = fmaxf(m_i[1], mx1);
            float f0 = exp2f(m_i[0] - mnew0);
            float f1 = exp2f(m_i[1] - mnew1);
            m_i[0] = mnew0; m_i[1] = mnew1;
            l_i[0] *= f0;   l_i[1] *= f1;
            #pragma unroll
            for (int nt = 0; nt < 8; nt++) {
                oacc[nt][0] *= f0; oacc[nt][1] *= f0;
                oacc[nt][2] *= f1; oacc[nt][3] *= f1;
            }

            float rs0 = 0.f, rs1 = 0.f;
            uint32_t ph[8][2];
            #pragma unroll
            for (int nt = 0; nt < 8; nt++) {
                float p0 = exp2f(sacc[nt][0] - mnew0);
                float p1 = exp2f(sacc[nt][1] - mnew0);
                float p2 = exp2f(sacc[nt][2] - mnew1);
                float p3 = exp2f(sacc[nt][3] - mnew1);
                rs0 += p0 + p1; rs1 += p2 + p3;
                __half2 lo = __floats2half2_rn(p0, p1);
                __half2 hi = __floats2half2_rn(p2, p3);
                ph[nt][0] = *(uint32_t*)&lo;
                ph[nt][1] = *(uint32_t*)&hi;
            }
            rs0 += __shfl_xor_sync(0xffffffffu, rs0, 1);
            rs0 += __shfl_xor_sync(0xffffffffu, rs0, 2);
            rs1 += __shfl_xor_sync(0xffffffffu, rs1, 1);
            rs1 += __shfl_xor_sync(0xffffffffu, rs1, 2);
            l_i[0] += rs0; l_i[1] += rs1;

            #pragma unroll
            for (int kk2 = 0; kk2 < 4; kk2++) {
                uint32_t ap[4];
                ap[0] = ph[2 * kk2][0];
                ap[1] = ph[2 * kk2][1];
                ap[2] = ph[2 * kk2 + 1][0];
                ap[3] = ph[2 * kk2 + 1][1];
                #pragma unroll
                for (int ntp = 0; ntp < 4; ntp++) {
                    int vrow = koff + kk2 * 16 + (t4 & 1) * 8 + r8;
                    int vcol = ntp * 16 + (t4 >> 1) * 8;
                    uint32_t addr = vbase + (uint32_t)(vrow * FQ_STRIDE + vcol) * 2u;
                    uint32_t r0, r1, r2, r3;
                    asm volatile(
                        "ldmatrix.sync.aligned.m8n8.x4.trans.shared.b16 {%0,%1,%2,%3}, [%4];"
                        : "=r"(r0), "=r"(r1), "=r"(r2), "=r"(r3) : "r"(addr));
                    mma16(oacc[2 * ntp],     ap, r0, r1);
                    mma16(oacc[2 * ntp + 1], ap, r2, r3);
                }
            }
        }
        __syncthreads();
    }

    float inv0 = 1.f / l_i[0];
    float inv1 = 1.f / l_i[1];
    __half2* C = (__half2*)(olin + (size_t)b * SEQ * DIM + h * HD);
    int row = m0 + warp * 16 + gid;
    #pragma unroll
    for (int nt = 0; nt < 8; nt++) {
        int col = nt * 8 + qid * 2;
        C[((size_t)row * DIM + col) >> 1] =
            __floats2half2_rn(oacc[nt][0] * inv0, oacc[nt][1] * inv0);
        C[((size_t)(row + 8) * DIM + col) >> 1] =
            __floats2half2_rn(oacc[nt][2] * inv1, oacc[nt][3] * inv1);
    }
}

// ---------------- launch ----------------
extern "C" void kernel_launch(void* const* d_in, const int* in_sizes, int n_in,
                              void* d_out, int out_size) {
    const float* x       = (const float*)d_in[0];
    const float* n1g     = (const float*)d_in[1];
    const float* n1b     = (const float*)d_in[2];
    const float* qkv_w   = (const float*)d_in[3];
    const float* qkv_b   = (const float*)d_in[4];
    const float* proj_w  = (const float*)d_in[5];
    const float* proj_b  = (const float*)d_in[6];
    const float* n2g     = (const float*)d_in[7];
    const float* n2b     = (const float*)d_in[8];
    const float* fc1_w   = (const float*)d_in[9];
    const float* fc1_b   = (const float*)d_in[10];
    const float* fc2_w   = (const float*)d_in[11];
    const float* fc2_b   = (const float*)d_in[12];
    float* out = (float*)d_out;

    __half *h1h, *h2h, *olinh, *h3h, *qkvh, *qkvwh, *projwh, *fc1wh, *fc2wh;
    float *x2;
    cudaGetSymbolAddress((void**)&h1h,    g_h1h);
    cudaGetSymbolAddress((void**)&h2h,    g_h2h);
    cudaGetSymbolAddress((void**)&olinh,  g_olinh);
    cudaGetSymbolAddress((void**)&h3h,    g_h3h);
    cudaGetSymbolAddress((void**)&qkvh,   g_qkvh);
    cudaGetSymbolAddress((void**)&x2,     g_x2);
    cudaGetSymbolAddress((void**)&qkvwh,  g_qkvwh);
    cudaGetSymbolAddress((void**)&projwh, g_projwh);
    cudaGetSymbolAddress((void**)&fc1wh,  g_fc1wh);
    cudaGetSymbolAddress((void**)&fc2wh,  g_fc2wh);

    cudaFuncSetAttribute(hgemm_tn_kernel<EPI_BIAS, 1, 128>,
                         cudaFuncAttributeMaxDynamicSharedMemorySize, GEMM_SMEM_128);
    cudaFuncSetAttribute(hgemm_tn_kernel<EPI_BIAS_GELU, 1, 128>,
                         cudaFuncAttributeMaxDynamicSharedMemorySize, GEMM_SMEM_128);
    cudaFuncSetAttribute(hgemm_tn_kernel<EPI_BIAS_RES, 0, 64>,
                         cudaFuncAttributeMaxDynamicSharedMemorySize, GEMM_SMEM_64);
    cudaFuncSetAttribute(flash_kernel,
                         cudaFuncAttributeMaxDynamicSharedMemorySize, FLASH_SMEM);

    // 0) all weights fp32 -> fp16, one launch
    const int n0 = QKVDIM*DIM/4, n1 = DIM*DIM/4, n2 = HIDDEN*DIM/4, n3 = DIM*HIDDEN/4;
    cvt_all<<<(n0+n1+n2+n3 + 255)/256, 256>>>(
        (const float4*)qkv_w,  (__half2*)qkvwh,  n0,
        (const float4*)proj_w, (__half2*)projwh, n1,
        (const float4*)fc1_w,  (__half2*)fc1wh,  n2,
        (const float4*)fc2_w,  (__half2*)fc2wh,  n3);

    // 1) LN1 -> fp16 (warp-per-row)
    ln_kernel<<<TOK/8, 256>>>(x, n1g, n1b, h1h);
    // 2) QKV = h1 @ qkv_w^T + b  (fp16 out)
    hgemm_tn_kernel<EPI_BIAS, 1, 128><<<dim3(QKVDIM/128, TOK/128), 256, GEMM_SMEM_128>>>(
        h1h, DIM, qkvwh, DIM, qkvh, QKVDIM, DIM, qkv_b, nullptr, 0);
    // 3) fused fp16 attention -> olin (fp16)
    flash_kernel<<<dim3(SEQ/128, NBH), 256, FLASH_SMEM>>>(qkvh, olinh);
    // 4) x2 = x + olin @ proj_w^T + b (fp32) — 64-row tiles vs wave quantization
    hgemm_tn_kernel<EPI_BIAS_RES, 0, 64><<<dim3(DIM/128, TOK/64), 256, GEMM_SMEM_64>>>(
        olinh, DIM, projwh, DIM, x2, DIM, DIM, proj_b, x, DIM);
    // 5) LN2 -> fp16
    ln_kernel<<<TOK/8, 256>>>(x2, n2g, n2b, h2h);
    // 6) h3 = gelu(h2 @ fc1_w^T + b) (fp16 out)
    hgemm_tn_kernel<EPI_BIAS_GELU, 1, 128><<<dim3(HIDDEN/128, TOK/128), 256, GEMM_SMEM_128>>>(
        h2h, DIM, fc1wh, DIM, h3h, HIDDEN, DIM, fc1_b, nullptr, 0);
    // 7) out = x2 + h3 @ fc2_w^T + b (fp32) — 64-row tiles
    hgemm_tn_kernel<EPI_BIAS_RES, 0, 64><<<dim3(DIM/128, TOK/64), 256, GEMM_SMEM_64>>>(
        h3h, HIDDEN, fc2wh, HIDDEN, out, DIM, HIDDEN, fc2_b, x2, DIM);
}

// round 16
// speedup vs baseline: 1.0546x; 1.0546x over previous
#include <cuda_runtime.h>
#include <cuda_fp16.h>
#include <math.h>
#include <stdint.h>

// Problem dims
#define DIM     768
#define HEADS   12
#define HD      64
#define HIDDEN  3072
#define SEQ     1024
#define BATCHN  8
#define TOK     (BATCHN*SEQ)   // 8192
#define QKVDIM  (3*DIM)        // 2304
#define NBH     (BATCHN*HEADS) // 96

// fp16 GEMM tiling: 3-stage cp.async ring, 128x128 CTA tile
#define BKH      64
#define HSTRIDE  72
#define STAGE_H  (128 * HSTRIDE)
#define GEMM_SMEM (3 * 2 * STAGE_H * 2)    // 110592 B -> 2 CTAs/SM

// fp16 flash smem (halves): Q | KV0(K,V) | KV1(K,V)
#define FQ_STRIDE 72
#define FTILE_H   (128 * FQ_STRIDE)
#define FLASH_SMEM (5 * FTILE_H * 2)       // 92160 B -> 2 CTAs/SM

#define LOG2E 1.44269504088896f

// ---------------- scratch ----------------
__device__ __half g_h1h[TOK*DIM];
__device__ __half g_h2h[TOK*DIM];
__device__ __half g_olinh[TOK*DIM];
__device__ __half g_h3h[(size_t)TOK*HIDDEN];
__device__ __half g_qkvh[(size_t)TOK*QKVDIM];
__device__ float  g_x2[TOK*DIM];
__device__ __half g_qkvwh[QKVDIM*DIM];
__device__ __half g_projwh[DIM*DIM];
__device__ __half g_fc1wh[HIDDEN*DIM];
__device__ __half g_fc2wh[DIM*HIDDEN];

// ---------------- helpers ----------------
__device__ __forceinline__ void mma16(float* d, const uint32_t* a, uint32_t b0, uint32_t b1) {
    asm volatile(
        "mma.sync.aligned.m16n8k16.row.col.f32.f16.f16.f32 "
        "{%0,%1,%2,%3}, {%4,%5,%6,%7}, {%8,%9}, {%0,%1,%2,%3};"
        : "+f"(d[0]), "+f"(d[1]), "+f"(d[2]), "+f"(d[3])
        : "r"(a[0]), "r"(a[1]), "r"(a[2]), "r"(a[3]), "r"(b0), "r"(b1));
}
__device__ __forceinline__ void ldsm4(uint32_t* r, uint32_t addr) {
    asm volatile("ldmatrix.sync.aligned.m8n8.x4.shared.b16 {%0,%1,%2,%3}, [%4];"
        : "=r"(r[0]), "=r"(r[1]), "=r"(r[2]), "=r"(r[3]) : "r"(addr));
}
__device__ __forceinline__ float gelu1(float x) {
    return 0.5f * x * (1.f + erff(x * 0.70710678118654752f));
}
__device__ __forceinline__ void cp16h(__half* dst, const __half* src) {
    unsigned d = (unsigned)__cvta_generic_to_shared(dst);
    asm volatile("cp.async.cg.shared.global [%0], [%1], 16;\n" :: "r"(d), "l"(src));
}
__device__ __forceinline__ void cp_commit() {
    asm volatile("cp.async.commit_group;\n");
}
template<int N>
__device__ __forceinline__ void cp_wait() {
    asm volatile("cp.async.wait_group %0;\n" :: "n"(N));
}

// ---------------- fused fp32 -> fp16 converter ----------------
__global__ void cvt_all(const float4* __restrict__ s0, __half2* __restrict__ d0, int n0,
                        const float4* __restrict__ s1, __half2* __restrict__ d1, int n1,
                        const float4* __restrict__ s2, __half2* __restrict__ d2, int n2,
                        const float4* __restrict__ s3, __half2* __restrict__ d3, int n3) {
    int i = blockIdx.x * blockDim.x + threadIdx.x;
    const float4* s; __half2* d;
    if (i < n0) { s = s0; d = d0; }
    else if ((i -= n0) < n1) { s = s1; d = d1; }
    else if ((i -= n1) < n2) { s = s2; d = d2; }
    else if ((i -= n2) < n3) { s = s3; d = d3; }
    else return;
    float4 v = s[i];
    d[2*i]   = __floats2half2_rn(v.x, v.y);
    d[2*i+1] = __floats2half2_rn(v.z, v.w);
}

// ---------------- LayerNorm: one warp per row, shuffle-only ----------------
__global__ void ln_kernel(const float* __restrict__ in,
                          const float* __restrict__ gam,
                          const float* __restrict__ bet,
                          __half* __restrict__ out) {
    const int warp = threadIdx.x >> 5, lane = threadIdx.x & 31;
    const int row = blockIdx.x * 8 + warp;
    const float* x = in + (size_t)row * DIM;

    float4 v[6];
    float s = 0.f, q = 0.f;
    #pragma unroll
    for (int i = 0; i < 6; i++) {
        v[i] = *(const float4*)(x + i * 128 + lane * 4);
        s += v[i].x + v[i].y + v[i].z + v[i].w;
        q += v[i].x*v[i].x + v[i].y*v[i].y + v[i].z*v[i].z + v[i].w*v[i].w;
    }
    #pragma unroll
    for (int o = 16; o > 0; o >>= 1) {
        s += __shfl_xor_sync(0xffffffffu, s, o);
        q += __shfl_xor_sync(0xffffffffu, q, o);
    }
    const float mu  = s * (1.0f / DIM);
    const float var = q * (1.0f / DIM) - mu * mu;
    const float inv = rsqrtf(var + 1e-5f);

    __half* o = out + (size_t)row * DIM;
    #pragma unroll
    for (int i = 0; i < 6; i++) {
        const int c = i * 128 + lane * 4;
        float4 g = *(const float4*)(gam + c);
        float4 b = *(const float4*)(bet + c);
        __half2 h0 = __floats2half2_rn((v[i].x - mu) * inv * g.x + b.x,
                                       (v[i].y - mu) * inv * g.y + b.y);
        __half2 h1 = __floats2half2_rn((v[i].z - mu) * inv * g.z + b.z,
                                       (v[i].w - mu) * inv * g.w + b.w);
        uint2 pk; pk.x = *(uint32_t*)&h0; pk.y = *(uint32_t*)&h1;
        *(uint2*)(o + c) = pk;
    }
}

// ---------------- FP16 MMA GEMM (TN): 3-stage ring, 128x128 (R14) ----------
enum { EPI_BIAS = 1, EPI_BIAS_RES = 2, EPI_BIAS_GELU = 3 };

template<int EPI, int OUTH>
__global__ __launch_bounds__(256, 2)
void hgemm_tn_kernel(const __half* __restrict__ A, int lda,
                     const __half* __restrict__ W, int ldw,
                     void* __restrict__ Cv, int ldc, int K,
                     const float* __restrict__ bias,
                     const float* __restrict__ res, int ldres) {
    extern __shared__ __half smh[];
    const uint32_t smbase = (uint32_t)__cvta_generic_to_shared(smh);
    const int m0 = blockIdx.y * 128, n0 = blockIdx.x * 128;
    const int tid  = threadIdx.x;
    const int lane = tid & 31;
    const int warp = tid >> 5;
    const int m0w  = (warp >> 2) * 64;
    const int n0w  = (warp & 3) * 32;
    const int gid  = lane >> 2;
    const int qid  = lane & 3;
    const int i8   = lane >> 3;
    const int r8   = lane & 7;

    const int crow0 = tid >> 3;
    const int cgr   = tid & 7;

    float acc[4][4][4];
    #pragma unroll
    for (int i = 0; i < 4; i++)
        #pragma unroll
        for (int j = 0; j < 4; j++)
            #pragma unroll
            for (int r = 0; r < 4; r++) acc[i][j][r] = 0.f;

    const int nch = K / BKH;

    auto load_chunk = [&](int j) {
        __half* as = smh + (j % 3) * 2 * STAGE_H;
        __half* ws = as + STAGE_H;
        const __half* Aj = A + (size_t)m0 * lda + j * BKH + cgr * 8;
        const __half* Wj = W + (size_t)n0 * ldw + j * BKH + cgr * 8;
        #pragma unroll
        for (int r = 0; r < 4; r++) {
            int row = crow0 + r * 32;
            cp16h(&as[row * HSTRIDE + cgr * 8], Aj + (size_t)row * lda);
            cp16h(&ws[row * HSTRIDE + cgr * 8], Wj + (size_t)row * ldw);
        }
    };

    load_chunk(0);
    cp_commit();
    load_chunk(1);
    cp_commit();

    for (int i = 0; i < nch; i++) {
        cp_wait<1>();
        __syncthreads();

        if (i + 2 < nch) load_chunk(i + 2);
        cp_commit();

        const uint32_t abase = smbase + ((i % 3) * 2 * STAGE_H) * 2;
        const uint32_t bbase = abase + STAGE_H * 2;
        #pragma unroll
        for (int ks = 0; ks < 4; ks++) {
            uint32_t af[4][4];
            #pragma unroll
            for (int mt = 0; mt < 4; mt++) {
                int row = m0w + mt * 16 + (i8 & 1) * 8 + r8;
                int kc  = ks * 16 + (i8 >> 1) * 8;
                ldsm4(af[mt], abase + (uint32_t)(row * HSTRIDE + kc) * 2u);
            }
            uint32_t bf[8];
            #pragma unroll
            for (int j = 0; j < 2; j++) {
                int nrow = n0w + (2 * j + (i8 >> 1)) * 8 + r8;
                int kc   = ks * 16 + (i8 & 1) * 8;
                ldsm4(&bf[4 * j], bbase + (uint32_t)(nrow * HSTRIDE + kc) * 2u);
            }
            #pragma unroll
            for (int nt = 0; nt < 4; nt++)
                #pragma unroll
                for (int mt = 0; mt < 4; mt++)
                    mma16(acc[mt][nt], af[mt], bf[nt * 2], bf[nt * 2 + 1]);
        }
    }

    #pragma unroll
    for (int mt = 0; mt < 4; mt++) {
        #pragma unroll
        for (int nt = 0; nt < 4; nt++) {
            int row = m0 + m0w + mt * 16 + gid;
            int col = n0 + n0w + nt * 8 + qid * 2;
            float2 v0, v1;
            v0.x = acc[mt][nt][0]; v0.y = acc[mt][nt][1];
            v1.x = acc[mt][nt][2]; v1.y = acc[mt][nt][3];
            {
                float2 bb = *(const float2*)(bias + col);
                v0.x += bb.x; v0.y += bb.y; v1.x += bb.x; v1.y += bb.y;
            }
            if (EPI == EPI_BIAS_RES) {
                float2 r0 = *(const float2*)(res + (size_t)row * ldres + col);
                float2 r1 = *(const float2*)(res + (size_t)(row + 8) * ldres + col);
                v0.x += r0.x; v0.y += r0.y; v1.x += r1.x; v1.y += r1.y;
            }
            if (EPI == EPI_BIAS_GELU) {
                v0.x = gelu1(v0.x); v0.y = gelu1(v0.y);
                v1.x = gelu1(v1.x); v1.y = gelu1(v1.y);
            }
            if (OUTH) {
                __half2* C = (__half2*)Cv;
                C[((size_t)row * ldc + col) >> 1]       = __floats2half2_rn(v0.x, v0.y);
                C[((size_t)(row + 8) * ldc + col) >> 1] = __floats2half2_rn(v1.x, v1.y);
            } else {
                float* C = (float*)Cv;
                *(float2*)(C + (size_t)row * ldc + col) = v0;
                *(float2*)(C + (size_t)(row + 8) * ldc + col) = v1;
            }
        }
    }
}

// ---------------- FP16 flash attention: reg-P + double-buffered KV (R14) ----------
__global__ __launch_bounds__(256, 2)
void flash_kernel(const __half* __restrict__ qkv, __half* __restrict__ olin) {
    extern __shared__ __half smf[];
    __half* Qs  = smf;
    __half* KV0 = Qs + FTILE_H;
    __half* KV1 = KV0 + 2 * FTILE_H;

    const int bh = blockIdx.y;
    const int b = bh / HEADS, h = bh % HEADS;
    const int m0 = blockIdx.x * 128;
    const __half* Qg = qkv + (size_t)b * SEQ * QKVDIM + h * HD;
    const __half* Kg = Qg + DIM;
    const __half* Vg = Qg + 2 * DIM;

    const int tid = threadIdx.x, lane = tid & 31, warp = tid >> 5;
    const int gid = lane >> 2, qid = lane & 3;
    const int i8 = lane >> 3, r8 = lane & 7;
    const int t4 = lane >> 3;

    const uint32_t qbase = (uint32_t)__cvta_generic_to_shared(Qs);

    auto load_kv = [&](int kc, __half* dst) {
        const __half* Kc = Kg + (size_t)(kc * 128) * QKVDIM;
        const __half* Vc = Vg + (size_t)(kc * 128) * QKVDIM;
        #pragma unroll
        for (int i = 0; i < 4; i++) {
            int f = i * 256 + tid;
            int r = f >> 3, c8 = (f & 7) * 8;
            cp16h(&dst[r * FQ_STRIDE + c8], Kc + (size_t)r * QKVDIM + c8);
            cp16h(&dst[FTILE_H + r * FQ_STRIDE + c8], Vc + (size_t)r * QKVDIM + c8);
        }
    };

    #pragma unroll
    for (int i = 0; i < 4; i++) {
        int f = i * 256 + tid;
        int r = f >> 3, c8 = (f & 7) * 8;
        cp16h(&Qs[r * FQ_STRIDE + c8], Qg + (size_t)(m0 + r) * QKVDIM + c8);
    }
    cp_commit();
    load_kv(0, KV0);
    cp_commit();

    cp_wait<1>();
    __syncthreads();

    const __half2 kscale = __floats2half2_rn(0.125f * LOG2E, 0.125f * LOG2E);
    uint32_t qf[4][4];
    #pragma unroll
    for (int kk = 0; kk < 4; kk++) {
        int row = warp * 16 + (i8 & 1) * 8 + r8;
        int kc  = kk * 16 + (i8 >> 1) * 8;
        ldsm4(qf[kk], qbase + (uint32_t)(row * FQ_STRIDE + kc) * 2u);
        #pragma unroll
        for (int r = 0; r < 4; r++) {
            __half2 t = __hmul2(*(__half2*)&qf[kk][r], kscale);
            qf[kk][r] = *(uint32_t*)&t;
        }
    }

    float m_i[2] = {-1e30f, -1e30f};
    float l_i[2] = {0.f, 0.f};
    float oacc[8][4];
    #pragma unroll
    for (int nt = 0; nt < 8; nt++)
        #pragma unroll
        for (int r = 0; r < 4; r++) oacc[nt][r] = 0.f;

    for (int kc = 0; kc < 8; kc++) {
        __half* cur = (kc & 1) ? KV1 : KV0;
        __half* nxt = (kc & 1) ? KV0 : KV1;

        if (kc + 1 < 8) load_kv(kc + 1, nxt);
        cp_commit();
        cp_wait<1>();
        __syncthreads();

        const uint32_t kbase = (uint32_t)__cvta_generic_to_shared(cur);
        const uint32_t vbase = kbase + (uint32_t)FTILE_H * 2u;

        #pragma unroll
        for (int half = 0; half < 2; half++) {
            const int koff = half * 64;

            float sacc[8][4];
            #pragma unroll
            for (int nt = 0; nt < 8; nt++)
                #pragma unroll
                for (int r = 0; r < 4; r++) sacc[nt][r] = 0.f;
            #pragma unroll
            for (int kk = 0; kk < 4; kk++) {
                #pragma unroll
                for (int j = 0; j < 4; j++) {
                    uint32_t bt[4];
                    int nrow = koff + (2 * j + (i8 >> 1)) * 8 + r8;
                    int kcc  = kk * 16 + (i8 & 1) * 8;
                    ldsm4(bt, kbase + (uint32_t)(nrow * FQ_STRIDE + kcc) * 2u);
                    mma16(sacc[2 * j],     qf[kk], bt[0], bt[1]);
                    mma16(sacc[2 * j + 1], qf[kk], bt[2], bt[3]);
                }
            }

            float mx0 = -1e30f, mx1 = -1e30f;
            #pragma unroll
            for (int nt = 0; nt < 8; nt++) {
                mx0 = fmaxf(mx0, fmaxf(sacc[nt][0], sacc[nt][1]));
                mx1 = fmaxf(mx1, fmaxf(sacc[nt][2], sacc[nt][3]));
            }
            mx0 = fmaxf(mx0, __shfl_xor_sync(0xffffffffu, mx0, 1));
            mx0 = fmaxf(mx0, __shfl_xor_sync(0xffffffffu, mx0, 2));
            mx1 = fmaxf(mx1, __shfl_xor_sync(0xffffffffu, mx1, 1));
            mx1 = fmaxf(mx1, __shfl_xor_sync(0xffffffffu, mx1, 2));

            float mnew0 = fmaxf(m_i[0], mx0);
            float mnew1 = fmaxf(m_i[1], mx1);
            float f0 = exp2f(m_i[0] - mnew0);
            float f1 = exp2f(m_i[1] - mnew1);
            m_i[0] = mnew0; m_i[1] = mnew1;
            l_i[0] *= f0;   l_i[1] *= f1;
            #pragma unroll
            for (int nt = 0; nt < 8; nt++) {
                oacc[nt][0] *= f0; oacc[nt][1] *= f0;
                oacc[nt][2] *= f1; oacc[nt][3] *= f1;
            }

            float rs0 = 0.f, rs1 = 0.f;
            uint32_t ph[8][2];
            #pragma unroll
            for (int nt = 0; nt < 8; nt++) {
                float p0 = exp2f(sacc[nt][0] - mnew0);
                float p1 = exp2f(sacc[nt][1] - mnew0);
                float p2 = exp2f(sacc[nt][2] - mnew1);
                float p3 = exp2f(sacc[nt][3] - mnew1);
                rs0 += p0 + p1; rs1 += p2 + p3;
                __half2 lo = __floats2half2_rn(p0, p1);
                __half2 hi = __floats2half2_rn(p2, p3);
                ph[nt][0] = *(uint32_t*)&lo;
                ph[nt][1] = *(uint32_t*)&hi;
            }
            rs0 += __shfl_xor_sync(0xffffffffu, rs0, 1);
            rs0 += __shfl_xor_sync(0xffffffffu, rs0, 2);
            rs1 += __shfl_xor_sync(0xffffffffu, rs1, 1);
            rs1 += __shfl_xor_sync(0xffffffffu, rs1, 2);
            l_i[0] += rs0; l_i[1] += rs1;

            #pragma unroll
            for (int kk2 = 0; kk2 < 4; kk2++) {
                uint32_t ap[4];
                ap[0] = ph[2 * kk2][0];
                ap[1] = ph[2 * kk2][1];
                ap[2] = ph[2 * kk2 + 1][0];
                ap[3] = ph[2 * kk2 + 1][1];
                #pragma unroll
                for (int ntp = 0; ntp < 4; ntp++) {
                    int vrow = koff + kk2 * 16 + (t4 & 1) * 8 + r8;
                    int vcol = ntp * 16 + (t4 >> 1) * 8;
                    uint32_t addr = vbase + (uint32_t)(vrow * FQ_STRIDE + vcol) * 2u;
                    uint32_t r0, r1, r2, r3;
                    asm volatile(
                        "ldmatrix.sync.aligned.m8n8.x4.trans.shared.b16 {%0,%1,%2,%3}, [%4];"
                        : "=r"(r0), "=r"(r1), "=r"(r2), "=r"(r3) : "r"(addr));
                    mma16(oacc[2 * ntp],     ap, r0, r1);
                    mma16(oacc[2 * ntp + 1], ap, r2, r3);
                }
            }
        }
        __syncthreads();
    }

    float inv0 = 1.f / l_i[0];
    float inv1 = 1.f / l_i[1];
    __half2* C = (__half2*)(olin + (size_t)b * SEQ * DIM + h * HD);
    int row = m0 + warp * 16 + gid;
    #pragma unroll
    for (int nt = 0; nt < 8; nt++) {
        int col = nt * 8 + qid * 2;
        C[((size_t)row * DIM + col) >> 1] =
            __floats2half2_rn(oacc[nt][0] * inv0, oacc[nt][1] * inv0);
        C[((size_t)(row + 8) * DIM + col) >> 1] =
            __floats2half2_rn(oacc[nt][2] * inv1, oacc[nt][3] * inv1);
    }
}

// ---------------- launch ----------------
extern "C" void kernel_launch(void* const* d_in, const int* in_sizes, int n_in,
                              void* d_out, int out_size) {
    const float* x       = (const float*)d_in[0];
    const float* n1g     = (const float*)d_in[1];
    const float* n1b     = (const float*)d_in[2];
    const float* qkv_w   = (const float*)d_in[3];
    const float* qkv_b   = (const float*)d_in[4];
    const float* proj_w  = (const float*)d_in[5];
    const float* proj_b  = (const float*)d_in[6];
    const float* n2g     = (const float*)d_in[7];
    const float* n2b     = (const float*)d_in[8];
    const float* fc1_w   = (const float*)d_in[9];
    const float* fc1_b   = (const float*)d_in[10];
    const float* fc2_w   = (const float*)d_in[11];
    const float* fc2_b   = (const float*)d_in[12];
    float* out = (float*)d_out;

    __half *h1h, *h2h, *olinh, *h3h, *qkvh, *qkvwh, *projwh, *fc1wh, *fc2wh;
    float *x2;
    cudaGetSymbolAddress((void**)&h1h,    g_h1h);
    cudaGetSymbolAddress((void**)&h2h,    g_h2h);
    cudaGetSymbolAddress((void**)&olinh,  g_olinh);
    cudaGetSymbolAddress((void**)&h3h,    g_h3h);
    cudaGetSymbolAddress((void**)&qkvh,   g_qkvh);
    cudaGetSymbolAddress((void**)&x2,     g_x2);
    cudaGetSymbolAddress((void**)&qkvwh,  g_qkvwh);
    cudaGetSymbolAddress((void**)&projwh, g_projwh);
    cudaGetSymbolAddress((void**)&fc1wh,  g_fc1wh);
    cudaGetSymbolAddress((void**)&fc2wh,  g_fc2wh);

    cudaFuncSetAttribute(hgemm_tn_kernel<EPI_BIAS, 1>,
                         cudaFuncAttributeMaxDynamicSharedMemorySize, GEMM_SMEM);
    cudaFuncSetAttribute(hgemm_tn_kernel<EPI_BIAS_RES, 0>,
                         cudaFuncAttributeMaxDynamicSharedMemorySize, GEMM_SMEM);
    cudaFuncSetAttribute(hgemm_tn_kernel<EPI_BIAS_GELU, 1>,
                         cudaFuncAttributeMaxDynamicSharedMemorySize, GEMM_SMEM);
    cudaFuncSetAttribute(flash_kernel,
                         cudaFuncAttributeMaxDynamicSharedMemorySize, FLASH_SMEM);

    // 0) all weights fp32 -> fp16, one launch
    const int n0 = QKVDIM*DIM/4, n1 = DIM*DIM/4, n2 = HIDDEN*DIM/4, n3 = DIM*HIDDEN/4;
    cvt_all<<<(n0+n1+n2+n3 + 255)/256, 256>>>(
        (const float4*)qkv_w,  (__half2*)qkvwh,  n0,
        (const float4*)proj_w, (__half2*)projwh, n1,
        (const float4*)fc1_w,  (__half2*)fc1wh,  n2,
        (const float4*)fc2_w,  (__half2*)fc2wh,  n3);

    // 1) LN1 -> fp16 (warp-per-row)
    ln_kernel<<<TOK/8, 256>>>(x, n1g, n1b, h1h);
    // 2) QKV = h1 @ qkv_w^T + b  (fp16 out)
    hgemm_tn_kernel<EPI_BIAS, 1><<<dim3(QKVDIM/128, TOK/128), 256, GEMM_SMEM>>>(
        h1h, DIM, qkvwh, DIM, qkvh, QKVDIM, DIM, qkv_b, nullptr, 0);
    // 3) fused fp16 attention -> olin (fp16)
    flash_kernel<<<dim3(SEQ/128, NBH), 256, FLASH_SMEM>>>(qkvh, olinh);
    // 4) x2 = x + olin @ proj_w^T + b (fp32)
    hgemm_tn_kernel<EPI_BIAS_RES, 0><<<dim3(DIM/128, TOK/128), 256, GEMM_SMEM>>>(
        olinh, DIM, projwh, DIM, x2, DIM, DIM, proj_b, x, DIM);
    // 5) LN2 -> fp16
    ln_kernel<<<TOK/8, 256>>>(x2, n2g, n2b, h2h);
    // 6) h3 = gelu(h2 @ fc1_w^T + b) (fp16 out)
    hgemm_tn_kernel<EPI_BIAS_GELU, 1><<<dim3(HIDDEN/128, TOK/128), 256, GEMM_SMEM>>>(
        h2h, DIM, fc1wh, DIM, h3h, HIDDEN, DIM, fc1_b, nullptr, 0);
    // 7) out = x2 + h3 @ fc2_w^T + b (fp32)
    hgemm_tn_kernel<EPI_BIAS_RES, 0><<<dim3(DIM/128, TOK/128), 256, GEMM_SMEM>>>(
        h3h, HIDDEN, fc2wh, HIDDEN, out, DIM, HIDDEN, fc2_b, x2, DIM);
}